// round 4
// baseline (speedup 1.0000x reference)
#include <cuda_runtime.h>
#include <cuda_fp16.h>
#include <cstdint>

#define NUM_USERS 200000
#define NUM_ITEMS 100000
#define N_NODES   (NUM_USERS + NUM_ITEMS)     // users first, then items (even)
#define EMB_DIM   64
#define ROW_U2    16                          // 16 uint2 (= 32 half2 = 128 B) per fp16 row
#define ROW_F4    16                          // 16 float4 (= 256 B) per fp32 row
#define MAX_EDGES 3000000

#define SCAN_TPB    1024
#define SCAN_BLOCKS ((N_NODES + SCAN_TPB - 1) / SCAN_TPB)   // 293

// ---------------------------------------------------------------------------
// Scratch (__device__ globals; no allocation allowed)
// ---------------------------------------------------------------------------
__device__ int   g_deg[N_NODES];
__device__ int   g_off[N_NODES];
__device__ int   g_cursor[N_NODES];
__device__ int   g_bsum[SCAN_BLOCKS];
__device__ int   g_bbase[SCAN_BLOCKS];
__device__ int   g_adj[2 * MAX_EDGES];                      // global node ids, 24 MB
__device__ uint2 g_h0[(size_t)N_NODES * ROW_U2];            // x0 fp16, 38.4 MB
__device__ uint2 g_h1[(size_t)N_NODES * ROW_U2];            // x1 fp16, 38.4 MB

// ---------------------------------------------------------------------------
// 0. zero degrees
// ---------------------------------------------------------------------------
__global__ void k_zerodeg() {
    int t = blockIdx.x * blockDim.x + threadIdx.x;
    int stride = gridDim.x * blockDim.x;
    for (int i = t; i < N_NODES; i += stride) g_deg[i] = 0;
}

// ---------------------------------------------------------------------------
// 1. degree histogram (both directions)
// ---------------------------------------------------------------------------
__global__ void k_count(const int* __restrict__ src, const int* __restrict__ dst,
                        int num_edges) {
    int e = blockIdx.x * blockDim.x + threadIdx.x;
    if (e >= num_edges) return;
    atomicAdd(&g_deg[src[e]], 1);
    atomicAdd(&g_deg[NUM_USERS + dst[e]], 1);
}

// ---------------------------------------------------------------------------
// 2-4. exclusive prefix scan over g_deg -> g_off
// ---------------------------------------------------------------------------
__global__ void k_scan1() {
    __shared__ int sh[SCAN_TPB];
    int tid = threadIdx.x;
    int gid = blockIdx.x * SCAN_TPB + tid;
    int v = (gid < N_NODES) ? g_deg[gid] : 0;
    sh[tid] = v;
    __syncthreads();
    for (int ofs = 1; ofs < SCAN_TPB; ofs <<= 1) {
        int t = 0;
        if (tid >= ofs) t = sh[tid - ofs];
        __syncthreads();
        sh[tid] += t;
        __syncthreads();
    }
    int incl = sh[tid];
    if (gid < N_NODES) g_off[gid] = incl - v;
    if (tid == SCAN_TPB - 1) g_bsum[blockIdx.x] = incl;
}

__global__ void k_scan2() {
    __shared__ int sh[512];
    int tid = threadIdx.x;
    int v = (tid < SCAN_BLOCKS) ? g_bsum[tid] : 0;
    sh[tid] = v;
    __syncthreads();
    for (int ofs = 1; ofs < 512; ofs <<= 1) {
        int t = 0;
        if (tid >= ofs) t = sh[tid - ofs];
        __syncthreads();
        sh[tid] += t;
        __syncthreads();
    }
    if (tid < SCAN_BLOCKS) g_bbase[tid] = sh[tid] - v;
}

__global__ void k_scan3() {
    int gid = blockIdx.x * SCAN_TPB + threadIdx.x;
    if (gid < N_NODES) {
        int v = g_off[gid] + g_bbase[blockIdx.x];
        g_off[gid]    = v;
        g_cursor[gid] = v;
    }
}

// ---------------------------------------------------------------------------
// 5. bin edges into combined CSR, storing GLOBAL node ids
// ---------------------------------------------------------------------------
__global__ void k_bin(const int* __restrict__ src, const int* __restrict__ dst,
                      int num_edges) {
    int e = blockIdx.x * blockDim.x + threadIdx.x;
    if (e >= num_edges) return;
    int s = src[e], d = dst[e];
    g_adj[atomicAdd(&g_cursor[s], 1)]             = NUM_USERS + d;
    g_adj[atomicAdd(&g_cursor[NUM_USERS + d], 1)] = s;
}

// ---------------------------------------------------------------------------
// 6. convert inputs to combined fp16 table (users then items)
// ---------------------------------------------------------------------------
__global__ void k_convert(const float4* __restrict__ u0, const float4* __restrict__ i0) {
    const long n   = (long)N_NODES * ROW_U2;
    const long n_u = (long)NUM_USERS * ROW_U2;
    long t = (long)blockIdx.x * blockDim.x + threadIdx.x;
    long stride = (long)gridDim.x * blockDim.x;
    for (long i = t; i < n; i += stride) {
        float4 v = (i < n_u) ? __ldg(&u0[i]) : __ldg(&i0[i - n_u]);
        __half2 lo = __floats2half2_rn(v.x, v.y);
        __half2 hi = __floats2half2_rn(v.z, v.w);
        g_h0[i] = make_uint2(*reinterpret_cast<uint32_t*>(&lo),
                             *reinterpret_cast<uint32_t*>(&hi));
    }
}

// ---------------------------------------------------------------------------
// 16-lane-group mean gather: each lane owns 8 B (uint2) of the 128 B fp16 row.
// Up to 8 gather loads in flight per group (16 per warp).
// ---------------------------------------------------------------------------
__device__ __forceinline__ float4 gather_mean16(int node, int gl,
                                                const uint2* __restrict__ tab) {
    int off = g_off[node];
    int deg = g_deg[node];
    float a0 = 0.f, a1 = 0.f, a2 = 0.f, a3 = 0.f;

    for (int base = 0; base < deg; base += 16) {
        int nidx = 0;
        if (base + gl < deg) nidx = __ldg(&g_adj[off + base + gl]);
        int lim = min(16, deg - base);
        int k = 0;
        for (; k + 8 <= lim; k += 8) {                        // 8 loads in flight
            int n[8];
            uint2 v[8];
#pragma unroll
            for (int j = 0; j < 8; j++)
                n[j] = __shfl_sync(0xffffffffu, nidx, k + j, 16);
#pragma unroll
            for (int j = 0; j < 8; j++)
                v[j] = __ldg(&tab[(long)n[j] * ROW_U2 + gl]);
#pragma unroll
            for (int j = 0; j < 8; j++) {
                float2 lo = __half22float2(*reinterpret_cast<__half2*>(&v[j].x));
                float2 hi = __half22float2(*reinterpret_cast<__half2*>(&v[j].y));
                a0 += lo.x; a1 += lo.y; a2 += hi.x; a3 += hi.y;
            }
        }
        for (; k < lim; k++) {
            int nb = __shfl_sync(0xffffffffu, nidx, k, 16);
            uint2 v = __ldg(&tab[(long)nb * ROW_U2 + gl]);
            float2 lo = __half22float2(*reinterpret_cast<__half2*>(&v.x));
            float2 hi = __half22float2(*reinterpret_cast<__half2*>(&v.y));
            a0 += lo.x; a1 += lo.y; a2 += hi.x; a3 += hi.y;
        }
    }
    float inv = deg > 0 ? 1.f / (float)deg : 0.f;
    return make_float4(a0 * inv, a1 * inv, a2 * inv, a3 * inv);
}

// ---------------------------------------------------------------------------
// 7. layer-1 pull: x1 = mean(x0 over neighbors), stored fp16. 2 nodes / warp.
// ---------------------------------------------------------------------------
__global__ void k_pull1() {
    int warp = (blockIdx.x * blockDim.x + threadIdx.x) >> 5;
    int lane = threadIdx.x & 31;
    int node = warp * 2 + (lane >> 4);
    int gl   = lane & 15;
    if (node >= N_NODES) return;

    float4 m = gather_mean16(node, gl, g_h0);
    __half2 lo = __floats2half2_rn(m.x, m.y);
    __half2 hi = __floats2half2_rn(m.z, m.w);
    g_h1[(long)node * ROW_U2 + gl] =
        make_uint2(*reinterpret_cast<uint32_t*>(&lo), *reinterpret_cast<uint32_t*>(&hi));
}

// ---------------------------------------------------------------------------
// 8. layer-2 pull fused with final combine:
//    out[n] = (x0_fp32 + x1_fp16 + mean_neighbors(x1_fp16)) / 3
// ---------------------------------------------------------------------------
__global__ void k_pull2(const float4* __restrict__ u0, const float4* __restrict__ i0,
                        float4* __restrict__ out) {
    int warp = (blockIdx.x * blockDim.x + threadIdx.x) >> 5;
    int lane = threadIdx.x & 31;
    int node = warp * 2 + (lane >> 4);
    int gl   = lane & 15;
    if (node >= N_NODES) return;

    float4 m = gather_mean16(node, gl, g_h1);                 // x2

    long idx = (long)node * ROW_F4 + gl;
    const long n_u = (long)NUM_USERS * ROW_F4;
    float4 a = (idx < n_u) ? __ldg(&u0[idx]) : __ldg(&i0[idx - n_u]);   // x0 fp32

    uint2 bv = g_h1[(long)node * ROW_U2 + gl];                          // x1 fp16
    float2 blo = __half22float2(*reinterpret_cast<__half2*>(&bv.x));
    float2 bhi = __half22float2(*reinterpret_cast<__half2*>(&bv.y));

    const float third = 1.0f / 3.0f;
    out[idx] = make_float4((a.x + blo.x + m.x) * third,
                           (a.y + blo.y + m.y) * third,
                           (a.z + bhi.x + m.z) * third,
                           (a.w + bhi.y + m.w) * third);
}

// ---------------------------------------------------------------------------
// kernel_launch
// ---------------------------------------------------------------------------
extern "C" void kernel_launch(void* const* d_in, const int* in_sizes, int n_in,
                              void* d_out, int out_size) {
    const float4* user_emb = (const float4*)d_in[0];
    const float4* item_emb = (const float4*)d_in[1];
    const int*    src      = (const int*)d_in[2];
    const int*    dst      = (const int*)d_in[3];
    const int     E        = in_sizes[2];
    float4*       out      = (float4*)d_out;

    const int TPB = 256;
    const int edge_blocks = (E + TPB - 1) / TPB;
    const long pull_threads = ((long)N_NODES / 2) * 32;       // 2 nodes per warp
    const int  pull_blocks  = (int)((pull_threads + TPB - 1) / TPB);

    k_zerodeg<<<256, TPB>>>();
    k_count<<<edge_blocks, TPB>>>(src, dst, E);
    k_scan1<<<SCAN_BLOCKS, SCAN_TPB>>>();
    k_scan2<<<1, 512>>>();
    k_scan3<<<SCAN_BLOCKS, SCAN_TPB>>>();
    k_bin<<<edge_blocks, TPB>>>(src, dst, E);
    k_convert<<<2048, TPB>>>(user_emb, item_emb);

    k_pull1<<<pull_blocks, TPB>>>();
    k_pull2<<<pull_blocks, TPB>>>(user_emb, item_emb, out);
}

// round 5
// speedup vs baseline: 1.0420x; 1.0420x over previous
#include <cuda_runtime.h>
#include <cuda_fp16.h>
#include <cstdint>

#define NUM_USERS 200000
#define NUM_ITEMS 100000
#define N_NODES   (NUM_USERS + NUM_ITEMS)     // users first, then items
#define EMB_DIM   64
#define H2        (EMB_DIM / 2)               // 32 half2 per fp16 row (128 B)
#define ROW_U2    16                          // 16 uint2 per fp16 row (for convert)
#define D2        (EMB_DIM / 2)
#define MAX_EDGES 3000000

#define SCAN_TPB    1024
#define SCAN_BLOCKS ((N_NODES + SCAN_TPB - 1) / SCAN_TPB)   // 293

// ---------------------------------------------------------------------------
// Scratch (__device__ globals; no allocation allowed)
// ---------------------------------------------------------------------------
__device__ int     g_deg[N_NODES];
__device__ int     g_off[N_NODES];
__device__ int     g_bsum[SCAN_BLOCKS];
__device__ int     g_bbase[SCAN_BLOCKS];
__device__ int     g_rank_s[MAX_EDGES];                      // slot of edge in src bucket
__device__ int     g_rank_d[MAX_EDGES];                      // slot of edge in dst bucket
__device__ int     g_adj[2 * MAX_EDGES];                     // global node ids, 24 MB
__device__ __half2 g_h0[(size_t)N_NODES * H2];               // x0 fp16, 38.4 MB
__device__ __half2 g_h1[(size_t)N_NODES * H2];               // x1 fp16, 38.4 MB

// ---------------------------------------------------------------------------
// 1. prep: zero degrees + convert x0 to combined fp16 table (one launch)
// ---------------------------------------------------------------------------
__global__ void k_prep(const float4* __restrict__ u0, const float4* __restrict__ i0) {
    const long n   = (long)N_NODES * ROW_U2;                 // 4.8M float4 -> uint2
    const long n_u = (long)NUM_USERS * ROW_U2;
    long t = (long)blockIdx.x * blockDim.x + threadIdx.x;
    long stride = (long)gridDim.x * blockDim.x;
    uint2* h0 = reinterpret_cast<uint2*>(g_h0);
    for (long i = t; i < n; i += stride) {
        float4 v = (i < n_u) ? __ldg(&u0[i]) : __ldg(&i0[i - n_u]);
        __half2 lo = __floats2half2_rn(v.x, v.y);
        __half2 hi = __floats2half2_rn(v.z, v.w);
        h0[i] = make_uint2(*reinterpret_cast<uint32_t*>(&lo),
                           *reinterpret_cast<uint32_t*>(&hi));
    }
    for (long i = t; i < N_NODES; i += stride) g_deg[i] = 0;
}

// ---------------------------------------------------------------------------
// 2. degree histogram; atomic return value = this edge's slot in the bucket
// ---------------------------------------------------------------------------
__global__ void k_count(const int* __restrict__ src, const int* __restrict__ dst,
                        int num_edges) {
    int e = blockIdx.x * blockDim.x + threadIdx.x;
    if (e >= num_edges) return;
    int s = __ldg(src + e), d = __ldg(dst + e);
    g_rank_s[e] = atomicAdd(&g_deg[s], 1);
    g_rank_d[e] = atomicAdd(&g_deg[NUM_USERS + d], 1);
}

// ---------------------------------------------------------------------------
// 3-5. exclusive prefix scan over g_deg -> g_off
// ---------------------------------------------------------------------------
__global__ void k_scan1() {
    __shared__ int sh[SCAN_TPB];
    int tid = threadIdx.x;
    int gid = blockIdx.x * SCAN_TPB + tid;
    int v = (gid < N_NODES) ? g_deg[gid] : 0;
    sh[tid] = v;
    __syncthreads();
    for (int ofs = 1; ofs < SCAN_TPB; ofs <<= 1) {
        int t = 0;
        if (tid >= ofs) t = sh[tid - ofs];
        __syncthreads();
        sh[tid] += t;
        __syncthreads();
    }
    int incl = sh[tid];
    if (gid < N_NODES) g_off[gid] = incl - v;
    if (tid == SCAN_TPB - 1) g_bsum[blockIdx.x] = incl;
}

__global__ void k_scan2() {
    __shared__ int sh[512];
    int tid = threadIdx.x;
    int v = (tid < SCAN_BLOCKS) ? g_bsum[tid] : 0;
    sh[tid] = v;
    __syncthreads();
    for (int ofs = 1; ofs < 512; ofs <<= 1) {
        int t = 0;
        if (tid >= ofs) t = sh[tid - ofs];
        __syncthreads();
        sh[tid] += t;
        __syncthreads();
    }
    if (tid < SCAN_BLOCKS) g_bbase[tid] = sh[tid] - v;
}

__global__ void k_scan3() {
    int gid = blockIdx.x * SCAN_TPB + threadIdx.x;
    if (gid < N_NODES) g_off[gid] += g_bbase[blockIdx.x];
}

// ---------------------------------------------------------------------------
// 6. bin edges into CSR — NO atomics (rank computed in k_count)
// ---------------------------------------------------------------------------
__global__ void k_bin(const int* __restrict__ src, const int* __restrict__ dst,
                      int num_edges) {
    int e = blockIdx.x * blockDim.x + threadIdx.x;
    if (e >= num_edges) return;
    int s = __ldg(src + e), d = __ldg(dst + e);
    int dn = NUM_USERS + d;
    g_adj[__ldg(&g_off[s])  + g_rank_s[e]] = dn;             // user row -> item node
    g_adj[__ldg(&g_off[dn]) + g_rank_d[e]] = s;              // item row -> user node
}

// ---------------------------------------------------------------------------
// Warp-level mean gather on fp16 table: one warp per node, half2 per lane
// (128 B per row LDG), fp32 accumulation, MLP=4.
// ---------------------------------------------------------------------------
__device__ __forceinline__ float2 gather_mean_h(int node, int lane,
                                                const __half2* __restrict__ tab) {
    int off = g_off[node];
    int deg = g_deg[node];
    float ax = 0.f, ay = 0.f;
    for (int base = 0; base < deg; base += 32) {
        int nidx = 0;
        if (base + lane < deg) nidx = __ldg(&g_adj[off + base + lane]);
        int lim = min(32, deg - base);
        int k = 0;
        for (; k + 4 <= lim; k += 4) {
            int n0 = __shfl_sync(0xffffffffu, nidx, k);
            int n1 = __shfl_sync(0xffffffffu, nidx, k + 1);
            int n2 = __shfl_sync(0xffffffffu, nidx, k + 2);
            int n3 = __shfl_sync(0xffffffffu, nidx, k + 3);
            float2 v0 = __half22float2(__ldg(&tab[(long)n0 * H2 + lane]));
            float2 v1 = __half22float2(__ldg(&tab[(long)n1 * H2 + lane]));
            float2 v2 = __half22float2(__ldg(&tab[(long)n2 * H2 + lane]));
            float2 v3 = __half22float2(__ldg(&tab[(long)n3 * H2 + lane]));
            ax += v0.x + v1.x + v2.x + v3.x;
            ay += v0.y + v1.y + v2.y + v3.y;
        }
        for (; k < lim; k++) {
            int nb = __shfl_sync(0xffffffffu, nidx, k);
            float2 v = __half22float2(__ldg(&tab[(long)nb * H2 + lane]));
            ax += v.x; ay += v.y;
        }
    }
    float inv = deg > 0 ? 1.f / (float)deg : 0.f;
    return make_float2(ax * inv, ay * inv);
}

// ---------------------------------------------------------------------------
// 7. layer-1 pull: x1 = mean(x0 over neighbors), stored fp16
// ---------------------------------------------------------------------------
__global__ void k_pull1() {
    int warp = (blockIdx.x * blockDim.x + threadIdx.x) >> 5;
    int lane = threadIdx.x & 31;
    if (warp >= N_NODES) return;
    float2 m = gather_mean_h(warp, lane, g_h0);
    g_h1[(long)warp * H2 + lane] = __float22half2_rn(m);
}

// ---------------------------------------------------------------------------
// 8. layer-2 pull fused with final combine:
//    out[n] = (x0_fp32 + x1_fp16 + mean_neighbors(x1_fp16)) / 3
// ---------------------------------------------------------------------------
__global__ void k_pull2(const float2* __restrict__ u0, const float2* __restrict__ i0,
                        float2* __restrict__ out) {
    int warp = (blockIdx.x * blockDim.x + threadIdx.x) >> 5;
    int lane = threadIdx.x & 31;
    if (warp >= N_NODES) return;

    float2 m = gather_mean_h(warp, lane, g_h1);               // x2

    long idx = (long)warp * D2 + lane;
    const long n_u = (long)NUM_USERS * D2;
    float2 a = (idx < n_u) ? __ldg(&u0[idx]) : __ldg(&i0[idx - n_u]);   // x0 fp32
    float2 b = __half22float2(__ldg(&g_h1[(long)warp * H2 + lane]));    // x1 fp16

    const float third = 1.0f / 3.0f;
    out[idx] = make_float2((a.x + b.x + m.x) * third, (a.y + b.y + m.y) * third);
}

// ---------------------------------------------------------------------------
// kernel_launch: 8 launches
// ---------------------------------------------------------------------------
extern "C" void kernel_launch(void* const* d_in, const int* in_sizes, int n_in,
                              void* d_out, int out_size) {
    const float4* user_emb4 = (const float4*)d_in[0];
    const float4* item_emb4 = (const float4*)d_in[1];
    const float2* user_emb2 = (const float2*)d_in[0];
    const float2* item_emb2 = (const float2*)d_in[1];
    const int*    src       = (const int*)d_in[2];
    const int*    dst       = (const int*)d_in[3];
    const int     E         = in_sizes[2];
    float2*       out       = (float2*)d_out;

    const int TPB = 256;
    const int edge_blocks = (E + TPB - 1) / TPB;
    const long pull_threads = (long)N_NODES * 32;
    const int  pull_blocks  = (int)((pull_threads + TPB - 1) / TPB);

    k_prep<<<2048, TPB>>>(user_emb4, item_emb4);
    k_count<<<edge_blocks, TPB>>>(src, dst, E);
    k_scan1<<<SCAN_BLOCKS, SCAN_TPB>>>();
    k_scan2<<<1, 512>>>();
    k_scan3<<<SCAN_BLOCKS, SCAN_TPB>>>();
    k_bin<<<edge_blocks, TPB>>>(src, dst, E);

    k_pull1<<<pull_blocks, TPB>>>();
    k_pull2<<<pull_blocks, TPB>>>(user_emb2, item_emb2, out);
}